// round 4
// baseline (speedup 1.0000x reference)
#include <cuda_runtime.h>
#include <math_constants.h>

#define NMAX 4096
#define TRACKS_PER_BLOCK 4
#define WARPS_PER_BLOCK (TRACKS_PER_BLOCK * 2)
#define BLOCK_THREADS (WARPS_PER_BLOCK * 32)
#define FULLMASK 0xffffffffu

// strict-less insert: within a lane, candidate j's arrive in ascending order,
// so strict < keeps the earlier index on exact ties (matches top_k stability).
#define TRY_INSERT(d2v, jv)                                        \
    do {                                                           \
        if ((d2v) < s1) {                                          \
            s3 = s2; i3 = i2; s2 = s1; i2 = i1;                    \
            if ((d2v) < s0) { s1 = s0; i1 = i0; s0 = (d2v); i0 = (jv); } \
            else            { s1 = (d2v); i1 = (jv); }             \
        } else {                                                   \
            if ((d2v) < s2) { s3 = s2; i3 = i2; s2 = (d2v); i2 = (jv); } \
            else            { s3 = (d2v); i3 = (jv); }             \
        }                                                          \
    } while (0)

// lexicographic (dist, idx) merge insert — exact tie-break to smallest index
#define LESSI(da, ja, db, jb) (((da) < (db)) || ((da) == (db) && (ja) < (jb)))
#define MERGE_INSERT(dv, jv)                                       \
    if (LESSI(dv, jv, s3, i3)) {                                   \
        if (LESSI(dv, jv, s1, i1)) {                               \
            s3 = s2; i3 = i2; s2 = s1; i2 = i1;                    \
            if (LESSI(dv, jv, s0, i0)) { s1 = s0; i1 = i0; s0 = (dv); i0 = (jv); } \
            else                       { s1 = (dv); i1 = (jv); }   \
        } else {                                                   \
            if (LESSI(dv, jv, s2, i2)) { s3 = s2; i3 = i2; s2 = (dv); i2 = (jv); } \
            else                       { s3 = (dv); i3 = (jv); }   \
        }                                                          \
    }

#define DPAIR(k)                                                   \
    {                                                              \
        float dx = xv[k] - pix, dy = yv[k] - piy;                  \
        d2[k] = fmaf(dx, dx, dy * dy);                             \
    }

__global__ __launch_bounds__(BLOCK_THREADS)
void nn_pool_kernel(const float* __restrict__ obs1,
                    const float* __restrict__ obs2,
                    const float* __restrict__ W,
                    const float* __restrict__ b,
                    float* __restrict__ out,
                    int n)
{
    // SoA: one LDS.128 yields 4 consecutive candidates per array
    __shared__ __align__(16) float sx[NMAX];
    __shared__ __align__(16) float sy[NMAX];
    __shared__ float sd[TRACKS_PER_BLOCK][4];   // cross-warp merge scratch
    __shared__ int   si[TRACKS_PER_BLOCK][4];

    const int tid = threadIdx.x;

    const float2* __restrict__ gpos = (const float2*)obs2;
    for (int t = tid; t < n; t += BLOCK_THREADS) {
        float2 p = gpos[t];
        sx[t] = p.x;
        sy[t] = p.y;
    }
    __syncthreads();

    const int warp = tid >> 5;
    const int lane = tid & 31;
    const int trk  = warp >> 1;           // track within block
    const int h    = warp & 1;            // half: which tiles this warp scans
    const int i    = blockIdx.x * TRACKS_PER_BLOCK + trk;
    const bool valid = (i < n);

    float s0 = CUDART_INF_F, s1 = CUDART_INF_F, s2 = CUDART_INF_F, s3 = CUDART_INF_F;
    int   i0 = n, i1 = n, i2 = n, i3 = n;

    if (valid) {
        const float pix = sx[i];
        const float piy = sy[i];

        // warp-shared prune threshold: thr = min over lanes of s3
        float thr = CUDART_INF_F;

        // tiles of 256 candidates; warp h takes tiles T ≡ h (mod 2);
        // lane covers 8 consecutive candidates per tile
        const int tiles = n >> 8;
        for (int T = h; T < tiles; T += 2) {
            const int j = (T << 8) + 8 * lane;
            float4 xa = *(const float4*)&sx[j];
            float4 xb = *(const float4*)&sx[j + 4];
            float4 ya = *(const float4*)&sy[j];
            float4 yb = *(const float4*)&sy[j + 4];
            float xv[8] = {xa.x, xa.y, xa.z, xa.w, xb.x, xb.y, xb.z, xb.w};
            float yv[8] = {ya.x, ya.y, ya.z, ya.w, yb.x, yb.y, yb.z, yb.w};
            float d2[8];
            #pragma unroll
            for (int k = 0; k < 8; ++k) DPAIR(k);

            float m = fminf(fminf(fminf(d2[0], d2[1]), fminf(d2[2], d2[3])),
                            fminf(fminf(d2[4], d2[5]), fminf(d2[6], d2[7])));

            if (__ballot_sync(FULLMASK, m < thr)) {
                if (m < s3) {
                    #pragma unroll
                    for (int k = 0; k < 8; ++k)
                        if (d2[k] < s3 && (j + k) != i) TRY_INSERT(d2[k], j + k);
                }
                float tm = s3;
                #pragma unroll
                for (int off = 16; off > 0; off >>= 1)
                    tm = fminf(tm, __shfl_xor_sync(FULLMASK, tm, off));
                thr = tm;
            }
        }

        // tail (n not a multiple of 256): warp h==0 handles it
        if (h == 0) {
            for (int j = (tiles << 8) + lane; j < n; j += 32) {
                float dx = sx[j] - pix;
                float dy = sy[j] - piy;
                float dd = fmaf(dx, dx, dy * dy);
                if (dd < s3 && j != i) TRY_INSERT(dd, j);
            }
        }

        // butterfly: every lane ends with this warp's half-global top-4
        #pragma unroll
        for (int off = 16; off > 0; off >>= 1) {
            float t0 = __shfl_xor_sync(FULLMASK, s0, off);
            float t1 = __shfl_xor_sync(FULLMASK, s1, off);
            float t2 = __shfl_xor_sync(FULLMASK, s2, off);
            float t3 = __shfl_xor_sync(FULLMASK, s3, off);
            int   u0 = __shfl_xor_sync(FULLMASK, i0, off);
            int   u1 = __shfl_xor_sync(FULLMASK, i1, off);
            int   u2 = __shfl_xor_sync(FULLMASK, i2, off);
            int   u3 = __shfl_xor_sync(FULLMASK, i3, off);
            MERGE_INSERT(t0, u0);
            MERGE_INSERT(t1, u1);
            MERGE_INSERT(t2, u2);
            MERGE_INSERT(t3, u3);
        }

        // half-1 publishes its top-4
        if (h == 1 && lane == 0) {
            sd[trk][0] = s0; sd[trk][1] = s1; sd[trk][2] = s2; sd[trk][3] = s3;
            si[trk][0] = i0; si[trk][1] = i1; si[trk][2] = i2; si[trk][3] = i3;
        }
    }

    __syncthreads();

    if (!valid || h == 1) return;

    // cross-warp merge: fold half-1's sorted 4 into half-0's top-4
    #pragma unroll
    for (int k = 0; k < 4; ++k) {
        float dv = sd[trk][k];
        int   jv = si[trk][k];
        MERGE_INSERT(dv, jv);
    }

    // epilogue: lane = k*8 + e computes out[i][k*8 + e]
    const float pix = sx[i];
    const float piy = sy[i];
    const int k = lane >> 3;
    const int e = lane & 7;
    int nj = (k == 0) ? i0 : (k == 1) ? i1 : (k == 2) ? i2 : i3;
    if (nj >= n) nj = n - 1;   // safety for degenerate n

    const float2* __restrict__ go1 = (const float2*)obs1;
    float pjx = sx[nj];
    float pjy = sy[nj];
    float2 o1j = go1[nj];
    float2 o1i = go1[i];

    float rpx = pjx - pix;
    float rpy = pjy - piy;
    float rvx = (pjx - o1j.x) - (pix - o1i.x);
    float rvy = (pjy - o1j.y) - (piy - o1i.y);

    float acc = b[e];
    acc = fmaf(rpx, W[0 * 8 + e], acc);
    acc = fmaf(rpy, W[1 * 8 + e], acc);
    acc = fmaf(rvx, W[2 * 8 + e], acc);
    acc = fmaf(rvy, W[3 * 8 + e], acc);

    out[i * 32 + lane] = fmaxf(acc, 0.0f);
}

extern "C" void kernel_launch(void* const* d_in, const int* in_sizes, int n_in,
                              void* d_out, int out_size) {
    const float* obs1 = (const float*)d_in[0];  // [N, 2]
    const float* obs2 = (const float*)d_in[1];  // [N, 2]
    const float* W    = (const float*)d_in[2];  // [4, 8]
    const float* b    = (const float*)d_in[3];  // [8]
    float* out = (float*)d_out;                  // [N, 32]

    int n = in_sizes[0] / 2;
    int blocks = (n + TRACKS_PER_BLOCK - 1) / TRACKS_PER_BLOCK;
    nn_pool_kernel<<<blocks, BLOCK_THREADS>>>(obs1, obs2, W, b, out, n);
}